// round 4
// baseline (speedup 1.0000x reference)
#include <cuda_runtime.h>
#include <cuda_fp16.h>
#include <math.h>
#include <stdint.h>

#define NN 32
#define VV 131072
#define NCHUNK 32
#define CTA_M 256

// smem: A tile [256 rows][128 B] at 0 (32 KB), B tile 8 KB at 32768. Total 40960.
// Epilogue reuses bytes [0, 33792) as float[64][132].
#define SMEM_TOTAL 40960

__device__ unsigned int g_max_bits;    // reset by kirch_init each launch
__device__ __half g_W[NCHUNK * 4096];  // W pre-swizzled per-chunk [np 64][k 64] SW128 tiles

static __device__ __forceinline__ uint32_t smem_u32(const void* p) {
    uint32_t a;
    asm("{ .reg .u64 t; cvta.to.shared.u64 t, %1; cvt.u32.u64 %0, t; }" : "=r"(a) : "l"(p));
    return a;
}

#define STS128U(a0, a1, a2, a3, addr) \
    asm volatile("st.shared.v4.b32 [%0], {%1,%2,%3,%4};" \
                 :: "r"(addr), "r"(a0), "r"(a1), "r"(a2), "r"(a3) : "memory")

#define LDMX4(d0, d1, d2, d3, addr) \
    asm volatile("ldmatrix.sync.aligned.m8n8.x4.shared.b16 {%0,%1,%2,%3}, [%4];" \
                 : "=r"(d0), "=r"(d1), "=r"(d2), "=r"(d3) : "r"(addr))

#define MMA16816(c, a0, a1, a2, a3, b0, b1) \
    asm volatile("mma.sync.aligned.m16n8k16.row.col.f32.f16.f16.f32 " \
                 "{%0,%1,%2,%3}, {%4,%5,%6,%7}, {%8,%9}, {%0,%1,%2,%3};" \
                 : "+f"((c)[0]), "+f"((c)[1]), "+f"((c)[2]), "+f"((c)[3]) \
                 : "r"(a0), "r"(a1), "r"(a2), "r"(a3), "r"(b0), "r"(b1))

extern "C" __global__ void kirch_init() { g_max_bits = 0u; }

// Build W[64 n', 2048 m] fp16 laid out exactly as the per-chunk SW128 smem tile bytes.
// m = ((t*8+r)*16 + k)*2 + comp; rows n'<32 -> Re (yre, -yim), n'>=32 -> Im (yim, yre).
extern "C" __global__ void kirch_prep(const float* __restrict__ yre,
                                      const float* __restrict__ yim) {
    int e = blockIdx.x * 256 + threadIdx.x;   // 0..131071
    int np = e >> 11;                          // n' 0..63
    int m = e & 2047;
    int comp = m & 1;
    int mm = m >> 1;
    int k = mm & 15;
    int tr = mm >> 4;
    int t = tr >> 3, r = tr & 7;
    int n = np & 31;
    int part = np >> 5;
    int yi = n * 1024 + k * 64 + t * 8 + r;
    float v;
    if (part == 0) v = comp ? -yim[yi] : yre[yi];
    else           v = comp ?  yre[yi] : yim[yi];
    int chunk = m >> 6;
    int j = m & 63;
    unsigned off = (unsigned)(np * 128 + j * 2);
    unsigned sw = off ^ ((off >> 3) & 0x70);
    g_W[chunk * 4096 + (sw >> 1)] = __float2half_rn(v);
}

extern "C" __global__ void __launch_bounds__(256, 2)
kirch_main(const float* __restrict__ freqs, const float* __restrict__ txp,
           const float* __restrict__ rxp, const float* __restrict__ xc,
           const float* __restrict__ yc, const float* __restrict__ zc,
           float* __restrict__ out)
{
    extern __shared__ unsigned char smem[];
    float* sfp = (float*)smem;
    const uint32_t sb = smem_u32(smem);
    const int tid = threadIdx.x;
    const int l = tid & 31;
    const int w = tid >> 5;

    const int v = blockIdx.x * CTA_M + tid;
    const int iz = v & 31;
    const int iy = (v >> 5) & 63;
    const int ix = v >> 11;
    const float px = xc[ix], py = yc[iy], pz = zc[iz];

    const float CC = (float)(2.0 * M_PI / 299792458.0);
    const float k0 = CC * freqs[0];
    const float dk = (CC * freqs[15] - k0) * (1.0f / 15.0f);

    float acc[64];   // [mt 2][nt 8][reg 4]
#pragma unroll
    for (int i = 0; i < 64; i++) acc[i] = 0.0f;

    // ldmatrix address components (constant across chunks)
    const uint32_t a_rb = sb + (uint32_t)((w * 32 + (l & 15)) * 128);  // + mt*2048
    const uint32_t b_rb = sb + 32768u + (uint32_t)((l & 15) * 128);    // + ng*2048
    const uint32_t sw7 = (uint32_t)(l & 7);
    const uint32_t u0 = (uint32_t)(l >> 4);
    const uint32_t rowoff = (uint32_t)(tid * 128);
    const uint32_t swx = (uint32_t)((tid & 7) << 4);

    for (int c = 0; c < NCHUNK; c++) {
        // stage B chunk (pre-swizzled): 8 KB, 512 float4 / 256 threads
        {
            const float4* src = (const float4*)(g_W + c * 4096);
            float4* dst = (float4*)(smem + 32768);
            dst[tid] = __ldg(src + tid);
            dst[256 + tid] = __ldg(src + 256 + tid);
        }

        // generate this thread's A row: 2 (t,r) pairs x 16 freqs, phase recurrence
        const int t = c >> 2;
        const int r0 = (c & 3) << 1;
        const float dxt = px - txp[t * 3 + 0];
        const float dyt = py - txp[t * 3 + 1];
        const float dzt = pz - txp[t * 3 + 2];
        const float Rt = sqrtf(dxt * dxt + dyt * dyt + dzt * dzt);
        const float bt = dzt / Rt;

#pragma unroll
        for (int p = 0; p < 2; p++) {
            const int r = r0 + p;
            const float dxr = px - rxp[r * 3 + 0];
            const float dyr = py - rxp[r * 3 + 1];
            const float dzr = pz - rxp[r * 3 + 2];
            const float Rr = sqrtf(dxr * dxr + dyr * dyr + dzr * dzr);
            const float br = dzr / Rr;
            const float g = 0.03125f * bt * br;   // 4 * 2^-7; cancels in normalization
            const float Rs = Rt + Rr;
            const float qq = g * Rt * Rr;
            const float gRs = g * Rs;

            float s0, c0, sd, cd;
            __sincosf(k0 * Rs, &s0, &c0);
            __sincosf(dk * Rs, &sd, &cd);
            float cr = c0, ci = s0;

            uint32_t q4[4];
#pragma unroll
            for (int k = 0; k < 16; k++) {
                float kj = fmaf((float)k, dk, k0);
                float are = fmaf(-qq, kj * kj, g);
                float aim = gRs * kj;
                float Are = fmaf(are, cr, -(aim * ci));
                float Aim = fmaf(are, ci, aim * cr);
                // advance rotation
                float ncr = fmaf(cr, cd, -(ci * sd));
                float nci = fmaf(cr, sd, ci * cd);
                cr = ncr; ci = nci;
                uint32_t hb;
                asm("cvt.rn.f16x2.f32 %0, %1, %2;" : "=r"(hb) : "f"(Aim), "f"(Are));
                q4[k & 3] = hb;
                if ((k & 3) == 3) {
                    uint32_t addr = sb + rowoff + ((uint32_t)((p << 6) + (k - 3) * 4) ^ swx);
                    STS128U(q4[0], q4[1], q4[2], q4[3], addr);
                }
            }
        }
        __syncthreads();

        // MMA: 4 k-steps of 16
#pragma unroll
        for (int ks = 0; ks < 4; ks++) {
            const uint32_t sx = (((u0 + (uint32_t)(ks * 2)) ^ sw7) << 4);
            uint32_t a0[4], a1[4];
            LDMX4(a0[0], a0[1], a0[2], a0[3], a_rb + sx);
            LDMX4(a1[0], a1[1], a1[2], a1[3], a_rb + 2048u + sx);
#pragma unroll
            for (int ng = 0; ng < 4; ng++) {
                uint32_t d0, d1, d2, d3;
                LDMX4(d0, d1, d2, d3, b_rb + (uint32_t)(ng * 2048) + sx);
                MMA16816(&acc[(0 * 8 + ng * 2 + 0) * 4], a0[0], a0[1], a0[2], a0[3], d0, d2);
                MMA16816(&acc[(0 * 8 + ng * 2 + 1) * 4], a0[0], a0[1], a0[2], a0[3], d1, d3);
                MMA16816(&acc[(1 * 8 + ng * 2 + 0) * 4], a1[0], a1[1], a1[2], a1[3], d0, d2);
                MMA16816(&acc[(1 * 8 + ng * 2 + 1) * 4], a1[0], a1[1], a1[2], a1[3], d1, d3);
            }
        }
        __syncthreads();
    }

    // ---- epilogue: transpose through smem, coalesced magnitude stores, global max ----
    float mx = 0.0f;
    const int outbase = blockIdx.x * CTA_M;
#pragma unroll
    for (int phase = 0; phase < 2; phase++) {
        if ((w >> 2) == phase) {
#pragma unroll
            for (int mt = 0; mt < 2; mt++)
#pragma unroll
                for (int nt = 0; nt < 8; nt++)
#pragma unroll
                    for (int rg = 0; rg < 4; rg++) {
                        int np = nt * 8 + 2 * (l & 3) + (rg & 1);
                        int vl = ((w & 3) * 32) + mt * 16 + (l >> 2) + ((rg >> 1) << 3);
                        sfp[np * 132 + vl] = acc[(mt * 8 + nt) * 4 + rg];
                    }
        }
        __syncthreads();
#pragma unroll
        for (int it = 0; it < 16; it++) {
            int idx = tid + it * 256;
            int n = idx >> 7;
            int vl = idx & 127;
            float re = sfp[n * 132 + vl];
            float im = sfp[(n + 32) * 132 + vl];
            float mag = sqrtf(re * re + im * im);
            out[n * VV + outbase + phase * 128 + vl] = mag;
            mx = fmaxf(mx, mag);
        }
        __syncthreads();
    }
#pragma unroll
    for (int o = 16; o > 0; o >>= 1)
        mx = fmaxf(mx, __shfl_xor_sync(0xffffffffu, mx, o));
    // one atomic per CTA: reduce warp maxima through smem
    if (l == 0) sfp[w] = mx;
    __syncthreads();
    if (tid == 0) {
        float bm = sfp[0];
#pragma unroll
        for (int i = 1; i < 8; i++) bm = fmaxf(bm, sfp[i]);
        atomicMax(&g_max_bits, __float_as_uint(bm));
    }
}

extern "C" __global__ void kirch_norm(float4* __restrict__ out) {
    const float inv = 1.0f / __uint_as_float(g_max_bits);
    int i = blockIdx.x * blockDim.x + threadIdx.x;   // 524288 threads, 2 float4 each
    float4 a = out[i];
    a.x *= inv; a.y *= inv; a.z *= inv; a.w *= inv;
    out[i] = a;
    int j = i + 524288;
    float4 b = out[j];
    b.x *= inv; b.y *= inv; b.z *= inv; b.w *= inv;
    out[j] = b;
}

extern "C" void kernel_launch(void* const* d_in, const int* in_sizes, int n_in,
                              void* d_out, int out_size) {
    const float* freqs = (const float*)d_in[0];
    const float* txp   = (const float*)d_in[1];
    const float* rxp   = (const float*)d_in[2];
    const float* xc    = (const float*)d_in[3];
    const float* yc    = (const float*)d_in[4];
    const float* zc    = (const float*)d_in[5];
    const float* yre   = (const float*)d_in[6];
    const float* yim   = (const float*)d_in[7];
    float* out = (float*)d_out;

    cudaFuncSetAttribute(kirch_main, cudaFuncAttributeMaxDynamicSharedMemorySize, SMEM_TOTAL);

    kirch_init<<<1, 1>>>();
    kirch_prep<<<512, 256>>>(yre, yim);
    kirch_main<<<VV / CTA_M, CTA_M, SMEM_TOTAL>>>(freqs, txp, rxp, xc, yc, zc, out);
    kirch_norm<<<2048, 256>>>((float4*)out);
}

// round 5
// speedup vs baseline: 1.2203x; 1.2203x over previous
#include <cuda_runtime.h>
#include <cuda_fp16.h>
#include <math.h>
#include <stdint.h>

#define NN 32
#define VV 131072
#define NCHUNK 32
#define CTA_M 256

// smem: A0 [0,32K), A1 [32K,64K), B0 [64K,72K), B1 [72K,80K)
// Epilogue reuses bytes [0, 33792) as float[64][132].
#define SM_A1 32768u
#define SM_B0 65536u
#define SM_B1 73728u
#define SMEM_TOTAL 81920

__device__ unsigned int g_max_bits;    // reset by kirch_init each launch
__device__ __half g_W[NCHUNK * 4096];  // W pre-swizzled per-chunk [np 64][k 64] SW128 tiles

static __device__ __forceinline__ uint32_t smem_u32(const void* p) {
    uint32_t a;
    asm("{ .reg .u64 t; cvta.to.shared.u64 t, %1; cvt.u32.u64 %0, t; }" : "=r"(a) : "l"(p));
    return a;
}

#define STS128U(a0, a1, a2, a3, addr) \
    asm volatile("st.shared.v4.b32 [%0], {%1,%2,%3,%4};" \
                 :: "r"(addr), "r"(a0), "r"(a1), "r"(a2), "r"(a3) : "memory")

#define LDMX4(d0, d1, d2, d3, addr) \
    asm volatile("ldmatrix.sync.aligned.m8n8.x4.shared.b16 {%0,%1,%2,%3}, [%4];" \
                 : "=r"(d0), "=r"(d1), "=r"(d2), "=r"(d3) : "r"(addr))

#define MMA16816(c, a0, a1, a2, a3, b0, b1) \
    asm volatile("mma.sync.aligned.m16n8k16.row.col.f32.f16.f16.f32 " \
                 "{%0,%1,%2,%3}, {%4,%5,%6,%7}, {%8,%9}, {%0,%1,%2,%3};" \
                 : "+f"((c)[0]), "+f"((c)[1]), "+f"((c)[2]), "+f"((c)[3]) \
                 : "r"(a0), "r"(a1), "r"(a2), "r"(a3), "r"(b0), "r"(b1))

extern "C" __global__ void kirch_init() { g_max_bits = 0u; }

// Build W[64 n', 2048 m] fp16 laid out exactly as the per-chunk SW128 smem tile bytes.
// m = ((t*8+r)*16 + k)*2 + comp; rows n'<32 -> Re (yre, -yim), n'>=32 -> Im (yim, yre).
extern "C" __global__ void kirch_prep(const float* __restrict__ yre,
                                      const float* __restrict__ yim) {
    int e = blockIdx.x * 256 + threadIdx.x;   // 0..131071
    int np = e >> 11;                          // n' 0..63
    int m = e & 2047;
    int comp = m & 1;
    int mm = m >> 1;
    int k = mm & 15;
    int tr = mm >> 4;
    int t = tr >> 3, r = tr & 7;
    int n = np & 31;
    int part = np >> 5;
    int yi = n * 1024 + k * 64 + t * 8 + r;
    float v;
    if (part == 0) v = comp ? -yim[yi] : yre[yi];
    else           v = comp ?  yre[yi] : yim[yi];
    int chunk = m >> 6;
    int j = m & 63;
    unsigned off = (unsigned)(np * 128 + j * 2);
    unsigned sw = off ^ ((off >> 3) & 0x70);
    g_W[chunk * 4096 + (sw >> 1)] = __float2half_rn(v);
}

extern "C" __global__ void __launch_bounds__(256)
kirch_main(const float* __restrict__ freqs, const float* __restrict__ txp,
           const float* __restrict__ rxp, const float* __restrict__ xc,
           const float* __restrict__ yc, const float* __restrict__ zc,
           float* __restrict__ out)
{
    extern __shared__ unsigned char smem[];
    float* sfp = (float*)smem;
    const uint32_t sb = smem_u32(smem);
    const int tid = threadIdx.x;
    const int l = tid & 31;
    const int w = tid >> 5;

    const int v = blockIdx.x * CTA_M + tid;
    const int iz = v & 31;
    const int iy = (v >> 5) & 63;
    const int ix = v >> 11;
    const float px = xc[ix], py = yc[iy], pz = zc[iz];

    const float CC = (float)(2.0 * M_PI / 299792458.0);
    const float k0 = CC * freqs[0];
    const float dk = (CC * freqs[15] - k0) * (1.0f / 15.0f);

    float acc[64];   // [mt 2][nt 8][reg 4]
#pragma unroll
    for (int i = 0; i < 64; i++) acc[i] = 0.0f;

    // ldmatrix address components (constant across chunks, + buffer offset)
    const uint32_t a_rb = sb + (uint32_t)((w * 32 + (l & 15)) * 128);  // + buf*32768 + mt*2048
    const uint32_t b_rb = sb + SM_B0 + (uint32_t)((l & 15) * 128);     // + buf*8192 + ng*2048
    const uint32_t sw7 = (uint32_t)(l & 7);
    const uint32_t u0 = (uint32_t)(l >> 4);
    const uint32_t rowoff = (uint32_t)(tid * 128);
    const uint32_t swx = (uint32_t)((tid & 7) << 4);

    for (int c = 0; c < NCHUNK; c++) {
        const uint32_t buf = (uint32_t)(c & 1);
        const uint32_t abase = sb + buf * SM_A1;
        // stage B chunk (pre-swizzled): 8 KB, 512 float4 / 256 threads
        {
            const float4* src = (const float4*)(g_W + c * 4096);
            float4* dst = (float4*)(smem + SM_B0 + buf * 8192u);
            dst[tid] = __ldg(src + tid);
            dst[256 + tid] = __ldg(src + 256 + tid);
        }

        // generate this thread's A row: 2 (t,r) pairs x 16 freqs, phase recurrence
        const int t = c >> 2;
        const int r0 = (c & 3) << 1;
        const float dxt = px - txp[t * 3 + 0];
        const float dyt = py - txp[t * 3 + 1];
        const float dzt = pz - txp[t * 3 + 2];
        const float Rt = sqrtf(dxt * dxt + dyt * dyt + dzt * dzt);
        const float bt = dzt / Rt;

#pragma unroll
        for (int p = 0; p < 2; p++) {
            const int r = r0 + p;
            const float dxr = px - rxp[r * 3 + 0];
            const float dyr = py - rxp[r * 3 + 1];
            const float dzr = pz - rxp[r * 3 + 2];
            const float Rr = sqrtf(dxr * dxr + dyr * dyr + dzr * dzr);
            const float br = dzr / Rr;
            const float g = 0.03125f * bt * br;   // 4 * 2^-7; cancels in normalization
            const float Rs = Rt + Rr;
            const float qq = g * Rt * Rr;
            const float gRs = g * Rs;

            float s0, c0, sd, cd;
            __sincosf(k0 * Rs, &s0, &c0);
            __sincosf(dk * Rs, &sd, &cd);
            float cr = c0, ci = s0;

            uint32_t q4[4];
#pragma unroll
            for (int k = 0; k < 16; k++) {
                float kj = fmaf((float)k, dk, k0);
                float are = fmaf(-qq, kj * kj, g);
                float aim = gRs * kj;
                float Are = fmaf(are, cr, -(aim * ci));
                float Aim = fmaf(are, ci, aim * cr);
                // advance rotation
                float ncr = fmaf(cr, cd, -(ci * sd));
                float nci = fmaf(cr, sd, ci * cd);
                cr = ncr; ci = nci;
                uint32_t hb;
                asm("cvt.rn.f16x2.f32 %0, %1, %2;" : "=r"(hb) : "f"(Aim), "f"(Are));
                q4[k & 3] = hb;
                if ((k & 3) == 3) {
                    uint32_t addr = abase + rowoff + ((uint32_t)((p << 6) + (k - 3) * 4) ^ swx);
                    STS128U(q4[0], q4[1], q4[2], q4[3], addr);
                }
            }
        }
        __syncthreads();   // single barrier per chunk: A[c]/B[c] ready; buffers freed 2 iters back

        // MMA: 4 k-steps of 16 (no trailing barrier -> overlaps next chunk's gen)
        const uint32_t a_mb = a_rb + buf * SM_A1;
        const uint32_t b_mb = b_rb + buf * 8192u;
#pragma unroll
        for (int ks = 0; ks < 4; ks++) {
            const uint32_t sx = (((u0 + (uint32_t)(ks * 2)) ^ sw7) << 4);
            uint32_t a0[4], a1[4];
            LDMX4(a0[0], a0[1], a0[2], a0[3], a_mb + sx);
            LDMX4(a1[0], a1[1], a1[2], a1[3], a_mb + 2048u + sx);
#pragma unroll
            for (int ng = 0; ng < 4; ng++) {
                uint32_t d0, d1, d2, d3;
                LDMX4(d0, d1, d2, d3, b_mb + (uint32_t)(ng * 2048) + sx);
                MMA16816(&acc[(0 * 8 + ng * 2 + 0) * 4], a0[0], a0[1], a0[2], a0[3], d0, d2);
                MMA16816(&acc[(0 * 8 + ng * 2 + 1) * 4], a0[0], a0[1], a0[2], a0[3], d1, d3);
                MMA16816(&acc[(1 * 8 + ng * 2 + 0) * 4], a1[0], a1[1], a1[2], a1[3], d0, d2);
                MMA16816(&acc[(1 * 8 + ng * 2 + 1) * 4], a1[0], a1[1], a1[2], a1[3], d1, d3);
            }
        }
    }

    __syncthreads();
    // ---- epilogue: transpose through smem, coalesced magnitude stores, global max ----
    float mx = 0.0f;
    const int outbase = blockIdx.x * CTA_M;
#pragma unroll
    for (int phase = 0; phase < 2; phase++) {
        if ((w >> 2) == phase) {
#pragma unroll
            for (int mt = 0; mt < 2; mt++)
#pragma unroll
                for (int nt = 0; nt < 8; nt++)
#pragma unroll
                    for (int rg = 0; rg < 4; rg++) {
                        int np = nt * 8 + 2 * (l & 3) + (rg & 1);
                        int vl = ((w & 3) * 32) + mt * 16 + (l >> 2) + ((rg >> 1) << 3);
                        sfp[np * 132 + vl] = acc[(mt * 8 + nt) * 4 + rg];
                    }
        }
        __syncthreads();
#pragma unroll
        for (int it = 0; it < 16; it++) {
            int idx = tid + it * 256;
            int n = idx >> 7;
            int vl = idx & 127;
            float re = sfp[n * 132 + vl];
            float im = sfp[(n + 32) * 132 + vl];
            float mag = sqrtf(re * re + im * im);
            out[n * VV + outbase + phase * 128 + vl] = mag;
            mx = fmaxf(mx, mag);
        }
        __syncthreads();
    }
#pragma unroll
    for (int o = 16; o > 0; o >>= 1)
        mx = fmaxf(mx, __shfl_xor_sync(0xffffffffu, mx, o));
    if (l == 0) sfp[w] = mx;
    __syncthreads();
    if (tid == 0) {
        float bm = sfp[0];
#pragma unroll
        for (int i = 1; i < 8; i++) bm = fmaxf(bm, sfp[i]);
        atomicMax(&g_max_bits, __float_as_uint(bm));
    }
}

extern "C" __global__ void kirch_norm(float4* __restrict__ out) {
    const float inv = 1.0f / __uint_as_float(g_max_bits);
    int i = blockIdx.x * blockDim.x + threadIdx.x;   // 1M float4, 1 each
    float4 a = out[i];
    a.x *= inv; a.y *= inv; a.z *= inv; a.w *= inv;
    out[i] = a;
}

extern "C" void kernel_launch(void* const* d_in, const int* in_sizes, int n_in,
                              void* d_out, int out_size) {
    const float* freqs = (const float*)d_in[0];
    const float* txp   = (const float*)d_in[1];
    const float* rxp   = (const float*)d_in[2];
    const float* xc    = (const float*)d_in[3];
    const float* yc    = (const float*)d_in[4];
    const float* zc    = (const float*)d_in[5];
    const float* yre   = (const float*)d_in[6];
    const float* yim   = (const float*)d_in[7];
    float* out = (float*)d_out;

    cudaFuncSetAttribute(kirch_main, cudaFuncAttributeMaxDynamicSharedMemorySize, SMEM_TOTAL);

    kirch_init<<<1, 1>>>();
    kirch_prep<<<512, 256>>>(yre, yim);
    kirch_main<<<VV / CTA_M, CTA_M, SMEM_TOTAL>>>(freqs, txp, rxp, xc, yc, zc, out);
    kirch_norm<<<4096, 256>>>((float4*)out);
}

// round 6
// speedup vs baseline: 1.6335x; 1.3386x over previous
#include <cuda_runtime.h>
#include <cuda_fp16.h>
#include <math.h>
#include <stdint.h>

#define NN 32
#define VV 131072
#define NCHUNK 32
#define CTA_M 128

// smem: A0 [0,16K), A1 [16K,32K), B0 [32K,40K), B1 [40K,48K)
// Epilogue reuses bytes [0, 33792) as float[64][132].
#define SM_A1 16384u
#define SM_B0 32768u
#define SMEM_TOTAL 49152

__device__ unsigned int g_max_bits;    // reset by kirch_init each launch
__device__ __half g_W[NCHUNK * 4096];  // W pre-swizzled per-chunk [np 64][k 64] SW128 tiles

static __device__ __forceinline__ uint32_t smem_u32(const void* p) {
    uint32_t a;
    asm("{ .reg .u64 t; cvta.to.shared.u64 t, %1; cvt.u32.u64 %0, t; }" : "=r"(a) : "l"(p));
    return a;
}

#define STS128U(a0, a1, a2, a3, addr) \
    asm volatile("st.shared.v4.b32 [%0], {%1,%2,%3,%4};" \
                 :: "r"(addr), "r"(a0), "r"(a1), "r"(a2), "r"(a3) : "memory")

#define LDMX4(d0, d1, d2, d3, addr) \
    asm volatile("ldmatrix.sync.aligned.m8n8.x4.shared.b16 {%0,%1,%2,%3}, [%4];" \
                 : "=r"(d0), "=r"(d1), "=r"(d2), "=r"(d3) : "r"(addr))

#define MMA16816(c, a0, a1, a2, a3, b0, b1) \
    asm volatile("mma.sync.aligned.m16n8k16.row.col.f32.f16.f16.f32 " \
                 "{%0,%1,%2,%3}, {%4,%5,%6,%7}, {%8,%9}, {%0,%1,%2,%3};" \
                 : "+f"((c)[0]), "+f"((c)[1]), "+f"((c)[2]), "+f"((c)[3]) \
                 : "r"(a0), "r"(a1), "r"(a2), "r"(a3), "r"(b0), "r"(b1))

extern "C" __global__ void kirch_init() { g_max_bits = 0u; }

// Build W[64 n', 2048 m] fp16 laid out exactly as the per-chunk SW128 smem tile bytes.
// m = ((t*8+r)*16 + k)*2 + comp; rows n'<32 -> Re (yre, -yim), n'>=32 -> Im (yim, yre).
extern "C" __global__ void kirch_prep(const float* __restrict__ yre,
                                      const float* __restrict__ yim) {
    int e = blockIdx.x * 256 + threadIdx.x;   // 0..131071
    int np = e >> 11;                          // n' 0..63
    int m = e & 2047;
    int comp = m & 1;
    int mm = m >> 1;
    int k = mm & 15;
    int tr = mm >> 4;
    int t = tr >> 3, r = tr & 7;
    int n = np & 31;
    int part = np >> 5;
    int yi = n * 1024 + k * 64 + t * 8 + r;
    float v;
    if (part == 0) v = comp ? -yim[yi] : yre[yi];
    else           v = comp ?  yre[yi] : yim[yi];
    int chunk = m >> 6;
    int j = m & 63;
    unsigned off = (unsigned)(np * 128 + j * 2);
    unsigned sw = off ^ ((off >> 3) & 0x70);
    g_W[chunk * 4096 + (sw >> 1)] = __float2half_rn(v);
}

extern "C" __global__ void __launch_bounds__(128)
kirch_main(const float* __restrict__ freqs, const float* __restrict__ txp,
           const float* __restrict__ rxp, const float* __restrict__ xc,
           const float* __restrict__ yc, const float* __restrict__ zc,
           float* __restrict__ out)
{
    extern __shared__ unsigned char smem[];
    float* sfp = (float*)smem;
    const uint32_t sb = smem_u32(smem);
    const int tid = threadIdx.x;
    const int l = tid & 31;
    const int w = tid >> 5;   // 0..3

    const int v = blockIdx.x * CTA_M + tid;
    const int iz = v & 31;
    const int iy = (v >> 5) & 63;
    const int ix = v >> 11;
    const float px = xc[ix], py = yc[iy], pz = zc[iz];

    const float CC = (float)(2.0 * M_PI / 299792458.0);
    const float k0 = CC * freqs[0];
    const float dk = (CC * freqs[15] - k0) * (1.0f / 15.0f);

    float acc[64];   // [mt 2][nt 8][reg 4]
#pragma unroll
    for (int i = 0; i < 64; i++) acc[i] = 0.0f;

    // ldmatrix address components (constant across chunks, + buffer offset)
    const uint32_t a_rb = sb + (uint32_t)((w * 32 + (l & 15)) * 128);  // + buf*16384 + mt*2048
    const uint32_t b_rb = sb + SM_B0 + (uint32_t)((l & 15) * 128);     // + buf*8192 + ng*2048
    const uint32_t sw7 = (uint32_t)(l & 7);
    const uint32_t u0 = (uint32_t)(l >> 4);
    const uint32_t rowoff = (uint32_t)(tid * 128);
    const uint32_t swx = (uint32_t)((tid & 7) << 4);

    // prefetch B chunk 0 into registers
    float4 bpre[4];
#pragma unroll
    for (int i = 0; i < 4; i++) bpre[i] = __ldg((const float4*)g_W + i * 128 + tid);

    for (int c = 0; c < NCHUNK; c++) {
        const uint32_t buf = (uint32_t)(c & 1);
        const uint32_t abase = sb + buf * SM_A1;

        // store prefetched B chunk (safe: mma(c-2) on this buf preceded sync(c-1))
        {
            float4* dst = (float4*)(smem + SM_B0 + buf * 8192u);
#pragma unroll
            for (int i = 0; i < 4; i++) dst[i * 128 + tid] = bpre[i];
        }

        // generate this thread's A row: 2 (t,r) pairs x 16 freqs, phase recurrence
        const int t = c >> 2;
        const int r0 = (c & 3) << 1;
        const float dxt = px - txp[t * 3 + 0];
        const float dyt = py - txp[t * 3 + 1];
        const float dzt = pz - txp[t * 3 + 2];
        const float Rt = sqrtf(dxt * dxt + dyt * dyt + dzt * dzt);
        const float bt = dzt / Rt;

#pragma unroll
        for (int p = 0; p < 2; p++) {
            const int r = r0 + p;
            const float dxr = px - rxp[r * 3 + 0];
            const float dyr = py - rxp[r * 3 + 1];
            const float dzr = pz - rxp[r * 3 + 2];
            const float Rr = sqrtf(dxr * dxr + dyr * dyr + dzr * dzr);
            const float br = dzr / Rr;
            const float g = 0.03125f * bt * br;   // 4 * 2^-7; cancels in normalization
            const float Rs = Rt + Rr;
            const float qq = g * Rt * Rr;
            const float gRs = g * Rs;

            float s0, c0, sd, cd;
            __sincosf(k0 * Rs, &s0, &c0);
            __sincosf(dk * Rs, &sd, &cd);
            float cr = c0, ci = s0;

            uint32_t q4[4];
#pragma unroll
            for (int k = 0; k < 16; k++) {
                float kj = fmaf((float)k, dk, k0);
                float are = fmaf(-qq, kj * kj, g);
                float aim = gRs * kj;
                float Are = fmaf(are, cr, -(aim * ci));
                float Aim = fmaf(are, ci, aim * cr);
                float ncr = fmaf(cr, cd, -(ci * sd));
                float nci = fmaf(cr, sd, ci * cd);
                cr = ncr; ci = nci;
                uint32_t hb;
                asm("cvt.rn.f16x2.f32 %0, %1, %2;" : "=r"(hb) : "f"(Aim), "f"(Are));
                q4[k & 3] = hb;
                if ((k & 3) == 3) {
                    uint32_t addr = abase + rowoff + ((uint32_t)((p << 6) + (k - 3) * 4) ^ swx);
                    STS128U(q4[0], q4[1], q4[2], q4[3], addr);
                }
            }
        }
        __syncthreads();   // single barrier per chunk

        // prefetch next B chunk (latency hides under MMA)
        if (c + 1 < NCHUNK) {
#pragma unroll
            for (int i = 0; i < 4; i++)
                bpre[i] = __ldg((const float4*)(g_W + (c + 1) * 4096) + i * 128 + tid);
        }

        // MMA: 4 k-steps of 16 (no trailing barrier -> overlaps next chunk's gen)
        const uint32_t a_mb = a_rb + buf * SM_A1;
        const uint32_t b_mb = b_rb + buf * 8192u;
#pragma unroll
        for (int ks = 0; ks < 4; ks++) {
            const uint32_t sx = (((u0 + (uint32_t)(ks * 2)) ^ sw7) << 4);
            uint32_t a0[4], a1[4];
            LDMX4(a0[0], a0[1], a0[2], a0[3], a_mb + sx);
            LDMX4(a1[0], a1[1], a1[2], a1[3], a_mb + 2048u + sx);
#pragma unroll
            for (int ng = 0; ng < 4; ng++) {
                uint32_t d0, d1, d2, d3;
                LDMX4(d0, d1, d2, d3, b_mb + (uint32_t)(ng * 2048) + sx);
                MMA16816(&acc[(0 * 8 + ng * 2 + 0) * 4], a0[0], a0[1], a0[2], a0[3], d0, d2);
                MMA16816(&acc[(0 * 8 + ng * 2 + 1) * 4], a0[0], a0[1], a0[2], a0[3], d1, d3);
                MMA16816(&acc[(1 * 8 + ng * 2 + 0) * 4], a1[0], a1[1], a1[2], a1[3], d0, d2);
                MMA16816(&acc[(1 * 8 + ng * 2 + 1) * 4], a1[0], a1[1], a1[2], a1[3], d1, d3);
            }
        }
    }

    __syncthreads();
    // ---- epilogue: transpose through smem (float[64][132]), coalesced stores ----
#pragma unroll
    for (int mt = 0; mt < 2; mt++)
#pragma unroll
        for (int nt = 0; nt < 8; nt++)
#pragma unroll
            for (int rg = 0; rg < 4; rg++) {
                int np = nt * 8 + 2 * (l & 3) + (rg & 1);
                int vl = w * 32 + mt * 16 + (l >> 2) + ((rg >> 1) << 3);
                sfp[np * 132 + vl] = acc[(mt * 8 + nt) * 4 + rg];
            }
    __syncthreads();

    float mx = 0.0f;
    const int outbase = blockIdx.x * CTA_M;
#pragma unroll
    for (int n = 0; n < NN; n++) {
        float re = sfp[n * 132 + tid];
        float im = sfp[(n + 32) * 132 + tid];
        float mag = sqrtf(re * re + im * im);
        out[n * VV + outbase + tid] = mag;
        mx = fmaxf(mx, mag);
    }
#pragma unroll
    for (int o = 16; o > 0; o >>= 1)
        mx = fmaxf(mx, __shfl_xor_sync(0xffffffffu, mx, o));
    __syncthreads();
    if (l == 0) sfp[w] = mx;
    __syncthreads();
    if (tid == 0) {
        float bm = fmaxf(fmaxf(sfp[0], sfp[1]), fmaxf(sfp[2], sfp[3]));
        atomicMax(&g_max_bits, __float_as_uint(bm));
    }
}

extern "C" __global__ void kirch_norm(float4* __restrict__ out) {
    const float inv = 1.0f / __uint_as_float(g_max_bits);
    int i = blockIdx.x * blockDim.x + threadIdx.x;   // 1M float4, 1 each
    float4 a = out[i];
    a.x *= inv; a.y *= inv; a.z *= inv; a.w *= inv;
    out[i] = a;
}

extern "C" void kernel_launch(void* const* d_in, const int* in_sizes, int n_in,
                              void* d_out, int out_size) {
    const float* freqs = (const float*)d_in[0];
    const float* txp   = (const float*)d_in[1];
    const float* rxp   = (const float*)d_in[2];
    const float* xc    = (const float*)d_in[3];
    const float* yc    = (const float*)d_in[4];
    const float* zc    = (const float*)d_in[5];
    const float* yre   = (const float*)d_in[6];
    const float* yim   = (const float*)d_in[7];
    float* out = (float*)d_out;

    cudaFuncSetAttribute(kirch_main, cudaFuncAttributeMaxDynamicSharedMemorySize, SMEM_TOTAL);

    kirch_init<<<1, 1>>>();
    kirch_prep<<<512, 256>>>(yre, yim);
    kirch_main<<<VV / CTA_M, CTA_M, SMEM_TOTAL>>>(freqs, txp, rxp, xc, yc, zc, out);
    kirch_norm<<<4096, 256>>>((float4*)out);
}

// round 7
// speedup vs baseline: 1.7700x; 1.0835x over previous
#include <cuda_runtime.h>
#include <cuda_fp16.h>
#include <math.h>
#include <stdint.h>

#define NN 32
#define VV 131072
#define NCHUNK 32
#define CTA_M 128

// smem: A0 [0,16K), A1 [16K,32K), B0 [32K,40K), B1 [40K,48K)
// Epilogue reuses bytes [0, 33792) as float[64][132].
#define SM_A1 16384u
#define SM_B0 32768u
#define SMEM_TOTAL 49152

__device__ unsigned int g_max_bits;    // reset by kirch_prep each launch
__device__ __half g_W[NCHUNK * 4096];  // W pre-swizzled per-chunk [np 64][k 64] SW128 tiles

typedef unsigned long long u64p;

static __device__ __forceinline__ uint32_t smem_u32(const void* p) {
    uint32_t a;
    asm("{ .reg .u64 t; cvta.to.shared.u64 t, %1; cvt.u32.u64 %0, t; }" : "=r"(a) : "l"(p));
    return a;
}
static __device__ __forceinline__ u64p pack2(float lo, float hi) {
    u64p r;
    asm("mov.b64 %0, {%1,%2};" : "=l"(r) : "f"(lo), "f"(hi));
    return r;
}
static __device__ __forceinline__ void unpack2(u64p v, float& lo, float& hi) {
    asm("mov.b64 {%0,%1}, %2;" : "=f"(lo), "=f"(hi) : "l"(v));
}
static __device__ __forceinline__ u64p mul2(u64p a, u64p b) {
    u64p r;
    asm("mul.rn.f32x2 %0, %1, %2;" : "=l"(r) : "l"(a), "l"(b));
    return r;
}
static __device__ __forceinline__ u64p add2(u64p a, u64p b) {
    u64p r;
    asm("add.rn.f32x2 %0, %1, %2;" : "=l"(r) : "l"(a), "l"(b));
    return r;
}
static __device__ __forceinline__ u64p fma2(u64p a, u64p b, u64p c) {
    u64p r;
    asm("fma.rn.f32x2 %0, %1, %2, %3;" : "=l"(r) : "l"(a), "l"(b), "l"(c));
    return r;
}

#define STS128U(a0, a1, a2, a3, addr) \
    asm volatile("st.shared.v4.b32 [%0], {%1,%2,%3,%4};" \
                 :: "r"(addr), "r"(a0), "r"(a1), "r"(a2), "r"(a3) : "memory")

#define LDMX4(d0, d1, d2, d3, addr) \
    asm volatile("ldmatrix.sync.aligned.m8n8.x4.shared.b16 {%0,%1,%2,%3}, [%4];" \
                 : "=r"(d0), "=r"(d1), "=r"(d2), "=r"(d3) : "r"(addr))

#define MMA16816(c, a0, a1, a2, a3, b0, b1) \
    asm volatile("mma.sync.aligned.m16n8k16.row.col.f32.f16.f16.f32 " \
                 "{%0,%1,%2,%3}, {%4,%5,%6,%7}, {%8,%9}, {%0,%1,%2,%3};" \
                 : "+f"((c)[0]), "+f"((c)[1]), "+f"((c)[2]), "+f"((c)[3]) \
                 : "r"(a0), "r"(a1), "r"(a2), "r"(a3), "r"(b0), "r"(b1))

// Build W[64 n', 2048 m] fp16 laid out exactly as the per-chunk SW128 smem tile bytes.
// m = ((t*8+r)*16 + k)*2 + comp; rows n'<32 -> Re (yre, -yim), n'>=32 -> Im (yim, yre).
extern "C" __global__ void kirch_prep(const float* __restrict__ yre,
                                      const float* __restrict__ yim) {
    if (blockIdx.x == 0 && threadIdx.x == 0) g_max_bits = 0u;
    int e = blockIdx.x * 256 + threadIdx.x;   // 0..131071
    int np = e >> 11;                          // n' 0..63
    int m = e & 2047;
    int comp = m & 1;
    int mm = m >> 1;
    int k = mm & 15;
    int tr = mm >> 4;
    int t = tr >> 3, r = tr & 7;
    int n = np & 31;
    int part = np >> 5;
    int yi = n * 1024 + k * 64 + t * 8 + r;
    float v;
    if (part == 0) v = comp ? -yim[yi] : yre[yi];
    else           v = comp ?  yre[yi] : yim[yi];
    int chunk = m >> 6;
    int j = m & 63;
    unsigned off = (unsigned)(np * 128 + j * 2);
    unsigned sw = off ^ ((off >> 3) & 0x70);
    g_W[chunk * 4096 + (sw >> 1)] = __float2half_rn(v);
}

extern "C" __global__ void __launch_bounds__(128)
kirch_main(const float* __restrict__ freqs, const float* __restrict__ txp,
           const float* __restrict__ rxp, const float* __restrict__ xc,
           const float* __restrict__ yc, const float* __restrict__ zc,
           float* __restrict__ out)
{
    extern __shared__ unsigned char smem[];
    float* sfp = (float*)smem;
    const uint32_t sb = smem_u32(smem);
    const int tid = threadIdx.x;
    const int l = tid & 31;
    const int w = tid >> 5;   // 0..3

    const int v = blockIdx.x * CTA_M + tid;
    const int iz = v & 31;
    const int iy = (v >> 5) & 63;
    const int ix = v >> 11;
    const float px = xc[ix], py = yc[iy], pz = zc[iz];

    const float CC = (float)(2.0 * M_PI / 299792458.0);
    const float k0 = CC * freqs[0];
    const float dk = (CC * freqs[15] - k0) * (1.0f / 15.0f);
    // hoisted amplitude-recurrence constants
    const float k00 = k0 * k0;
    const float c_d2 = -2.0f * dk * dk;            // * qq
    const float c_d1 = -dk * (2.0f * k0 + dk);     // * qq

    float acc[64];   // [mt 2][nt 8][reg 4]
#pragma unroll
    for (int i = 0; i < 64; i++) acc[i] = 0.0f;

    // ldmatrix address components (constant across chunks, + buffer offset)
    const uint32_t a_rb = sb + (uint32_t)((w * 32 + (l & 15)) * 128);  // + buf*16384 + mt*2048
    const uint32_t b_rb = sb + SM_B0 + (uint32_t)((l & 15) * 128);     // + buf*8192 + ng*2048
    const uint32_t sw7 = (uint32_t)(l & 7);
    const uint32_t u0 = (uint32_t)(l >> 4);
    const uint32_t rowoff = (uint32_t)(tid * 128);
    const uint32_t swx = (uint32_t)((tid & 7) << 4);

    // prefetch B chunk 0 into registers
    float4 bpre[4];
#pragma unroll
    for (int i = 0; i < 4; i++) bpre[i] = __ldg((const float4*)g_W + i * 128 + tid);

    for (int c = 0; c < NCHUNK; c++) {
        const uint32_t buf = (uint32_t)(c & 1);
        const uint32_t abase = sb + buf * SM_A1;

        // store prefetched B chunk (safe: mma(c-2) on this buf preceded sync(c-1))
        {
            float4* dst = (float4*)(smem + SM_B0 + buf * 8192u);
#pragma unroll
            for (int i = 0; i < 4; i++) dst[i * 128 + tid] = bpre[i];
        }

        // generate this thread's A row: 2 (t,r) pairs x 16 freqs, packed f32x2 math
        const int t = c >> 2;
        const int r0 = (c & 3) << 1;
        const float dxt = px - txp[t * 3 + 0];
        const float dyt = py - txp[t * 3 + 1];
        const float dzt = pz - txp[t * 3 + 2];
        const float Rt = sqrtf(dxt * dxt + dyt * dyt + dzt * dzt);
        const float bt = dzt / Rt;

#pragma unroll
        for (int p = 0; p < 2; p++) {
            const int r = r0 + p;
            const float dxr = px - rxp[r * 3 + 0];
            const float dyr = py - rxp[r * 3 + 1];
            const float dzr = pz - rxp[r * 3 + 2];
            const float Rr = sqrtf(dxr * dxr + dyr * dyr + dzr * dzr);
            const float br = dzr / Rr;
            const float g = 0.03125f * bt * br;   // 4 * 2^-7; cancels in normalization
            const float Rs = Rt + Rr;
            const float qq = g * Rt * Rr;
            const float gRs = g * Rs;

            float s0, c0, sd, cd;
            __sincosf(k0 * Rs, &s0, &c0);
            __sincosf(dk * Rs, &sd, &cd);

            // packed state
            u64p uu  = pack2(c0, s0);          // (cr, ci)
            u64p us  = pack2(s0, c0);          // (ci, cr)
            u64p cdp = pack2(cd, cd);
            u64p sdm = pack2(-sd, sd);
            float are0 = fmaf(-qq, k00, g);
            u64p arep = pack2(are0, are0);
            float d1v = qq * c_d1;
            u64p d1p = pack2(d1v, d1v);
            float d2v = qq * c_d2;
            u64p d2p = pack2(d2v, d2v);
            float aim0 = gRs * k0;
            float daim = gRs * dk;
            u64p am   = pack2(-aim0, aim0);
            u64p damp = pack2(-daim, daim);

            uint32_t q4[4];
#pragma unroll
            for (int k = 0; k < 16; k++) {
                // A = (are + i*aim) * (cr + i*ci): 2 packed ops
                u64p A = fma2(arep, uu, mul2(am, us));
                // rotate phase: 2 packed ops + register swap
                u64p un = fma2(cdp, uu, mul2(sdm, us));
                float ncr, nci;
                unpack2(un, ncr, nci);
                uu = un;
                us = pack2(nci, ncr);
                // amplitude recurrences: 3 packed adds
                arep = add2(arep, d1p);
                d1p  = add2(d1p, d2p);
                am   = add2(am, damp);

                float Are, Aim;
                unpack2(A, Are, Aim);
                uint32_t hb;
                asm("cvt.rn.f16x2.f32 %0, %1, %2;" : "=r"(hb) : "f"(Aim), "f"(Are));
                q4[k & 3] = hb;
                if ((k & 3) == 3) {
                    uint32_t addr = abase + rowoff + ((uint32_t)((p << 6) + (k - 3) * 4) ^ swx);
                    STS128U(q4[0], q4[1], q4[2], q4[3], addr);
                }
            }
        }
        __syncthreads();   // single barrier per chunk

        // prefetch next B chunk (latency hides under MMA)
        if (c + 1 < NCHUNK) {
#pragma unroll
            for (int i = 0; i < 4; i++)
                bpre[i] = __ldg((const float4*)(g_W + (c + 1) * 4096) + i * 128 + tid);
        }

        // MMA: 4 k-steps of 16 (no trailing barrier -> overlaps next chunk's gen)
        const uint32_t a_mb = a_rb + buf * SM_A1;
        const uint32_t b_mb = b_rb + buf * 8192u;
#pragma unroll
        for (int ks = 0; ks < 4; ks++) {
            const uint32_t sx = (((u0 + (uint32_t)(ks * 2)) ^ sw7) << 4);
            uint32_t a0[4], a1[4];
            LDMX4(a0[0], a0[1], a0[2], a0[3], a_mb + sx);
            LDMX4(a1[0], a1[1], a1[2], a1[3], a_mb + 2048u + sx);
#pragma unroll
            for (int ng = 0; ng < 4; ng++) {
                uint32_t d0, d1, d2, d3;
                LDMX4(d0, d1, d2, d3, b_mb + (uint32_t)(ng * 2048) + sx);
                MMA16816(&acc[(0 * 8 + ng * 2 + 0) * 4], a0[0], a0[1], a0[2], a0[3], d0, d2);
                MMA16816(&acc[(0 * 8 + ng * 2 + 1) * 4], a0[0], a0[1], a0[2], a0[3], d1, d3);
                MMA16816(&acc[(1 * 8 + ng * 2 + 0) * 4], a1[0], a1[1], a1[2], a1[3], d0, d2);
                MMA16816(&acc[(1 * 8 + ng * 2 + 1) * 4], a1[0], a1[1], a1[2], a1[3], d1, d3);
            }
        }
    }

    __syncthreads();
    // ---- epilogue: transpose through smem (float[64][132]), coalesced stores ----
#pragma unroll
    for (int mt = 0; mt < 2; mt++)
#pragma unroll
        for (int nt = 0; nt < 8; nt++)
#pragma unroll
            for (int rg = 0; rg < 4; rg++) {
                int np = nt * 8 + 2 * (l & 3) + (rg & 1);
                int vl = w * 32 + mt * 16 + (l >> 2) + ((rg >> 1) << 3);
                sfp[np * 132 + vl] = acc[(mt * 8 + nt) * 4 + rg];
            }
    __syncthreads();

    float mx = 0.0f;
    const int outbase = blockIdx.x * CTA_M;
#pragma unroll
    for (int n = 0; n < NN; n++) {
        float re = sfp[n * 132 + tid];
        float im = sfp[(n + 32) * 132 + tid];
        float mag = sqrtf(re * re + im * im);
        out[n * VV + outbase + tid] = mag;
        mx = fmaxf(mx, mag);
    }
#pragma unroll
    for (int o = 16; o > 0; o >>= 1)
        mx = fmaxf(mx, __shfl_xor_sync(0xffffffffu, mx, o));
    __syncthreads();
    if (l == 0) sfp[w] = mx;
    __syncthreads();
    if (tid == 0) {
        float bm = fmaxf(fmaxf(sfp[0], sfp[1]), fmaxf(sfp[2], sfp[3]));
        atomicMax(&g_max_bits, __float_as_uint(bm));
    }
}

extern "C" __global__ void kirch_norm(float4* __restrict__ out) {
    const float inv = 1.0f / __uint_as_float(g_max_bits);
    int i = blockIdx.x * blockDim.x + threadIdx.x;   // 1M float4, 1 each
    float4 a = out[i];
    a.x *= inv; a.y *= inv; a.z *= inv; a.w *= inv;
    out[i] = a;
}

extern "C" void kernel_launch(void* const* d_in, const int* in_sizes, int n_in,
                              void* d_out, int out_size) {
    const float* freqs = (const float*)d_in[0];
    const float* txp   = (const float*)d_in[1];
    const float* rxp   = (const float*)d_in[2];
    const float* xc    = (const float*)d_in[3];
    const float* yc    = (const float*)d_in[4];
    const float* zc    = (const float*)d_in[5];
    const float* yre   = (const float*)d_in[6];
    const float* yim   = (const float*)d_in[7];
    float* out = (float*)d_out;

    cudaFuncSetAttribute(kirch_main, cudaFuncAttributeMaxDynamicSharedMemorySize, SMEM_TOTAL);

    kirch_prep<<<512, 256>>>(yre, yim);
    kirch_main<<<VV / CTA_M, CTA_M, SMEM_TOTAL>>>(freqs, txp, rxp, xc, yc, zc, out);
    kirch_norm<<<4096, 256>>>((float4*)out);
}